// round 10
// baseline (speedup 1.0000x reference)
#include <cuda_runtime.h>
#include <cstdint>

// AFM forward: 2 samples per CTA, thread t handles pairs t and t+138 SEQUENTIALLY
// (lower register pressure -> 4 CTAs/SM). Hidden GEMV uses packed fma.rn.f32x2.
// cross term = (sum_p e^{s_p} g_p) / (sum_p e^{s_p}),  g_p = inner_p . fc_w

#define NF 24
#define NE 16
#define NA 32
#define NP 276            // 24*23/2
#define NS 2              // samples per block
#define HPT 138           // thread t handles pairs t and t+HPT
#define NTHREADS 160      // 5 warps
#define NWARP 5
#define EPAD 20           // padded row length for s_emb (80B)

typedef unsigned long long u64;

__device__ __forceinline__ u64 pack2(float lo, float hi) {
    u64 r;
    asm("mov.b64 %0, {%1, %2};" : "=l"(r) : "f"(lo), "f"(hi));
    return r;
}
__device__ __forceinline__ void unpack2(u64 v, float& lo, float& hi) {
    asm("mov.b64 {%0, %1}, %2;" : "=f"(lo), "=f"(hi) : "l"(v));
}
__device__ __forceinline__ u64 fma2(u64 a, u64 b, u64 c) {
    u64 d;
    asm("fma.rn.f32x2 %0, %1, %2, %3;" : "=l"(d) : "l"(a), "l"(b), "l"(c));
    return d;
}

// Full per-pair pipeline for both samples: inner products, g, MLP, score.
__device__ __forceinline__ void compute_pair(
    int r, int c,
    const float* __restrict__ emb0,    // s_emb[0] base, rows of EPAD floats
    const float* __restrict__ emb1,    // s_emb[1] base
    const float* __restrict__ sW,      // [16][32]
    const float* __restrict__ sb,      // [32]
    const float* __restrict__ sp,      // [32]
    const float* __restrict__ sfc,     // [16]
    float projb,
    float& sc0, float& sc1, float& g0, float& g1)
{
    float in0[NE], in1[NE];
    const float4* er0 = (const float4*)(emb0 + r * EPAD);
    const float4* ec0 = (const float4*)(emb0 + c * EPAD);
    const float4* er1 = (const float4*)(emb1 + r * EPAD);
    const float4* ec1 = (const float4*)(emb1 + c * EPAD);
    #pragma unroll
    for (int q = 0; q < 4; q++) {
        float4 a0 = er0[q], c0v = ec0[q];
        float4 a1 = er1[q], c1v = ec1[q];
        in0[q*4+0]=a0.x*c0v.x; in0[q*4+1]=a0.y*c0v.y; in0[q*4+2]=a0.z*c0v.z; in0[q*4+3]=a0.w*c0v.w;
        in1[q*4+0]=a1.x*c1v.x; in1[q*4+1]=a1.y*c1v.y; in1[q*4+2]=a1.z*c1v.z; in1[q*4+3]=a1.w*c1v.w;
    }

    g0 = 0.f; g1 = 0.f;
    #pragma unroll
    for (int e = 0; e < NE; e++) {
        float fw = sfc[e];
        g0 = fmaf(in0[e], fw, g0);
        g1 = fmaf(in1[e], fw, g1);
    }

    float s0 = projb, s1 = projb;
    #pragma unroll
    for (int ch = 0; ch < 4; ch++) {
        const u64* bb = (const u64*)&sb[ch*8];
        u64 h0[4], h1[4];
        #pragma unroll
        for (int j = 0; j < 4; j++) { u64 bj = bb[j]; h0[j] = bj; h1[j] = bj; }

        #pragma unroll
        for (int e = 0; e < NE; e++) {
            const u64* wr = (const u64*)&sW[e*NA + ch*8];
            u64 i0 = pack2(in0[e], in0[e]);
            u64 i1 = pack2(in1[e], in1[e]);
            #pragma unroll
            for (int j = 0; j < 4; j++) {
                u64 w = wr[j];
                h0[j] = fma2(i0, w, h0[j]);
                h1[j] = fma2(i1, w, h1[j]);
            }
        }

        #pragma unroll
        for (int j = 0; j < 4; j++) {
            float p0 = sp[ch*8 + j*2 + 0];
            float p1 = sp[ch*8 + j*2 + 1];
            float lo, hi;
            unpack2(h0[j], lo, hi);
            s0 = fmaf(fmaxf(lo,0.f), p0, s0);
            s0 = fmaf(fmaxf(hi,0.f), p1, s0);
            unpack2(h1[j], lo, hi);
            s1 = fmaf(fmaxf(lo,0.f), p0, s1);
            s1 = fmaf(fmaxf(hi,0.f), p1, s1);
        }
    }
    sc0 = s0; sc1 = s1;
}

__global__ __launch_bounds__(NTHREADS, 4) void afm_kernel(
    const int* __restrict__ x_raw,            // [B,24] int32 OR int64 (auto-detect)
    const float* __restrict__ embed_table,    // [V,16]
    const float* __restrict__ linear_table,   // [V,1]
    const float* __restrict__ linear_bias,    // [1]
    const float* __restrict__ attn_W,         // [16,32]
    const float* __restrict__ attn_b,         // [32]
    const float* __restrict__ proj_w,         // [32,1]
    const float* __restrict__ proj_b,         // [1]
    const float* __restrict__ fc_w,           // [16,1]
    const float* __restrict__ fc_b,           // [1]
    float* __restrict__ out)                  // [B,1]
{
    __shared__ __align__(16) float s_emb[NS][NF][EPAD];
    __shared__ __align__(16) float s_W[NE][NA];
    __shared__ __align__(16) float s_attnb[NA];
    __shared__ __align__(16) float s_projw[NA];
    __shared__ __align__(16) float s_fcw[NE];
    __shared__ int   s_gid[NS][NF];
    __shared__ float s_lin[NS][NF];
    __shared__ float s_scal[2];
    __shared__ float red_max[NS][NWARP];
    __shared__ float red_se[NS][NWARP];
    __shared__ float red_sg[NS][NWARP];
    __shared__ float s_smax[NS];

    const int tid  = threadIdx.x;
    const int wid  = tid >> 5;
    const int lane = tid & 31;
    const long long b0 = (long long)blockIdx.x * NS;

    // dtype probe: int64 values < 50000 have zero high words at odd positions.
    const bool is64 = (x_raw[1] == 0) & (x_raw[3] == 0) & (x_raw[5] == 0) & (x_raw[7] == 0);

    // ---- stage indices + linear terms ----
    if (tid < NS * NF) {
        int s = tid / NF;
        int f = tid - s * NF;
        long long flat = (b0 + s) * NF + f;
        int xv = is64 ? x_raw[flat * 2] : x_raw[flat];
        int gid = xv + f * 50000;
        s_gid[s][f] = gid;
        s_lin[s][f] = linear_table[gid];
    }
    for (int t = tid; t < NE * NA; t += NTHREADS)
        ((float*)s_W)[t] = attn_W[t];
    if (tid < NA) {
        s_attnb[tid] = attn_b[tid];
        s_projw[tid] = proj_w[tid];
    }
    if (tid < NE) s_fcw[tid] = fc_w[tid];
    if (tid == 0) {
        s_scal[0] = proj_b[0];
        s_scal[1] = fc_b[0] + linear_bias[0];
    }
    __syncthreads();

    // ---- gather embeddings as float4 ----
    for (int t = tid; t < NS * NF * 4; t += NTHREADS) {
        int s = t / (NF * 4);
        int rem = t - s * (NF * 4);
        int f = rem >> 2, q = rem & 3;
        const float4* src = (const float4*)embed_table;
        ((float4*)&s_emb[s][f][0])[q] = src[(long long)s_gid[s][f] * 4 + q];
    }
    __syncthreads();

    // ---- per-thread: pairs A=tid, B=tid+HPT, processed sequentially ----
    const bool active = (tid < HPT);
    float scA0 = -1e30f, scA1 = -1e30f, scB0 = -1e30f, scB1 = -1e30f;
    float gA0 = 0.f, gA1 = 0.f, gB0 = 0.f, gB1 = 0.f;

    if (active) {
        const float projb = s_scal[0];
        // pair A
        {
            int p = tid, r = 0, base = 0;
            while (p >= base + (NF - 1 - r)) { base += NF - 1 - r; r++; }
            int c = r + 1 + (p - base);
            compute_pair(r, c, &s_emb[0][0][0], &s_emb[1][0][0],
                         &s_W[0][0], s_attnb, s_projw, s_fcw, projb,
                         scA0, scA1, gA0, gA1);
        }
        // pair B
        {
            int p = tid + HPT, r = 0, base = 0;
            while (p >= base + (NF - 1 - r)) { base += NF - 1 - r; r++; }
            int c = r + 1 + (p - base);
            compute_pair(r, c, &s_emb[0][0][0], &s_emb[1][0][0],
                         &s_W[0][0], s_attnb, s_projw, s_fcw, projb,
                         scB0, scB1, gB0, gB1);
        }
    }

    // ---- block softmax-max reduction (both samples) ----
    float m0 = fmaxf(scA0, scB0);
    float m1 = fmaxf(scA1, scB1);
    #pragma unroll
    for (int o = 16; o > 0; o >>= 1) {
        m0 = fmaxf(m0, __shfl_xor_sync(0xffffffffu, m0, o));
        m1 = fmaxf(m1, __shfl_xor_sync(0xffffffffu, m1, o));
    }
    if (lane == 0) { red_max[0][wid] = m0; red_max[1][wid] = m1; }
    __syncthreads();
    if (tid == 0) {
        float a = red_max[0][0], b = red_max[1][0];
        #pragma unroll
        for (int w = 1; w < NWARP; w++) {
            a = fmaxf(a, red_max[0][w]);
            b = fmaxf(b, red_max[1][w]);
        }
        s_smax[0] = a; s_smax[1] = b;
    }
    __syncthreads();

    // ---- exp + weighted sums ----
    const float smax0 = s_smax[0], smax1 = s_smax[1];
    float exA0 = active ? __expf(scA0 - smax0) : 0.f;
    float exA1 = active ? __expf(scA1 - smax1) : 0.f;
    float exB0 = active ? __expf(scB0 - smax0) : 0.f;
    float exB1 = active ? __expf(scB1 - smax1) : 0.f;
    float se0 = exA0 + exB0;
    float se1 = exA1 + exB1;
    float sg0 = exA0 * gA0 + exB0 * gB0;
    float sg1 = exA1 * gA1 + exB1 * gB1;
    #pragma unroll
    for (int o = 16; o > 0; o >>= 1) {
        se0 += __shfl_xor_sync(0xffffffffu, se0, o);
        sg0 += __shfl_xor_sync(0xffffffffu, sg0, o);
        se1 += __shfl_xor_sync(0xffffffffu, se1, o);
        sg1 += __shfl_xor_sync(0xffffffffu, sg1, o);
    }
    if (lane == 0) {
        red_se[0][wid] = se0; red_sg[0][wid] = sg0;
        red_se[1][wid] = se1; red_sg[1][wid] = sg1;
    }
    __syncthreads();

    if (tid < NS) {
        int s = tid;
        float tse = 0.f, tsg = 0.f;
        #pragma unroll
        for (int w = 0; w < NWARP; w++) { tse += red_se[s][w]; tsg += red_sg[s][w]; }
        float lin = 0.f;
        #pragma unroll
        for (int f = 0; f < NF; f++) lin += s_lin[s][f];
        out[b0 + s] = lin + s_scal[1] + tsg / tse;
    }
}

extern "C" void kernel_launch(void* const* d_in, const int* in_sizes, int n_in,
                              void* d_out, int out_size) {
    const int* x              = (const int*)d_in[0];
    const float* embed_table  = (const float*)d_in[1];
    const float* linear_table = (const float*)d_in[2];
    const float* linear_bias  = (const float*)d_in[3];
    const float* attn_W       = (const float*)d_in[4];
    const float* attn_b       = (const float*)d_in[5];
    const float* proj_w       = (const float*)d_in[6];
    const float* proj_b       = (const float*)d_in[7];
    const float* fc_w         = (const float*)d_in[8];
    const float* fc_b         = (const float*)d_in[9];
    float* out = (float*)d_out;

    int B = out_size;                 // one output per sample
    int nblocks = (B + NS - 1) / NS;  // 16384 -> 8192
    afm_kernel<<<nblocks, NTHREADS>>>(x, embed_table, linear_table, linear_bias,
                                      attn_W, attn_b, proj_w, proj_b, fc_w, fc_b, out);
}

// round 11
// speedup vs baseline: 7.7625x; 7.7625x over previous
#include <cuda_runtime.h>
#include <cstdint>

// AFM forward: 2 samples per CTA, 2 pairs x 2 samples per thread (interleaved
// 4-stream R9 structure), hidden GEMV via packed fma.rn.f32x2, chunked as
// 8 chunks x 4 attn cols (small accumulators -> 4 CTAs/SM without spills).
// cross term = (sum_p e^{s_p} g_p) / (sum_p e^{s_p}),  g_p = inner_p . fc_w

#define NF 24
#define NE 16
#define NA 32
#define NP 276            // 24*23/2
#define NS 2              // samples per block
#define HPT 138           // thread t handles pairs t and t+HPT
#define NTHREADS 160      // 5 warps
#define NWARP 5
#define EPAD 20           // padded row length for s_emb (80B)

typedef unsigned long long u64;

__device__ __forceinline__ u64 pack2(float lo, float hi) {
    u64 r;
    asm("mov.b64 %0, {%1, %2};" : "=l"(r) : "f"(lo), "f"(hi));
    return r;
}
__device__ __forceinline__ void unpack2(u64 v, float& lo, float& hi) {
    asm("mov.b64 {%0, %1}, %2;" : "=f"(lo), "=f"(hi) : "l"(v));
}
__device__ __forceinline__ u64 fma2(u64 a, u64 b, u64 c) {
    u64 d;
    asm("fma.rn.f32x2 %0, %1, %2, %3;" : "=l"(d) : "l"(a), "l"(b), "l"(c));
    return d;
}

__global__ __launch_bounds__(NTHREADS, 4) void afm_kernel(
    const int* __restrict__ x_raw,            // [B,24] int32 OR int64 (auto-detect)
    const float* __restrict__ embed_table,    // [V,16]
    const float* __restrict__ linear_table,   // [V,1]
    const float* __restrict__ linear_bias,    // [1]
    const float* __restrict__ attn_W,         // [16,32]
    const float* __restrict__ attn_b,         // [32]
    const float* __restrict__ proj_w,         // [32,1]
    const float* __restrict__ proj_b,         // [1]
    const float* __restrict__ fc_w,           // [16,1]
    const float* __restrict__ fc_b,           // [1]
    float* __restrict__ out)                  // [B,1]
{
    __shared__ __align__(16) float s_emb[NS][NF][EPAD];
    __shared__ __align__(16) float s_W[NE][NA];
    __shared__ __align__(16) float s_attnb[NA];
    __shared__ __align__(16) float s_projw[NA];
    __shared__ __align__(16) float s_fcw[NE];
    __shared__ int   s_gid[NS][NF];
    __shared__ float s_lin[NS][NF];
    __shared__ float s_scal[2];
    __shared__ float red_max[NS][NWARP];
    __shared__ float red_se[NS][NWARP];
    __shared__ float red_sg[NS][NWARP];
    __shared__ float s_smax[NS];

    const int tid  = threadIdx.x;
    const int wid  = tid >> 5;
    const int lane = tid & 31;
    const long long b0 = (long long)blockIdx.x * NS;

    // dtype probe: int64 values < 50000 have zero high words at odd positions.
    const bool is64 = (x_raw[1] == 0) & (x_raw[3] == 0) & (x_raw[5] == 0) & (x_raw[7] == 0);

    // ---- stage indices + linear terms ----
    if (tid < NS * NF) {
        int s = tid / NF;
        int f = tid - s * NF;
        long long flat = (b0 + s) * NF + f;
        int xv = is64 ? x_raw[flat * 2] : x_raw[flat];
        int gid = xv + f * 50000;
        s_gid[s][f] = gid;
        s_lin[s][f] = linear_table[gid];
    }
    for (int t = tid; t < NE * NA; t += NTHREADS)
        ((float*)s_W)[t] = attn_W[t];
    if (tid < NA) {
        s_attnb[tid] = attn_b[tid];
        s_projw[tid] = proj_w[tid];
    }
    if (tid < NE) s_fcw[tid] = fc_w[tid];
    if (tid == 0) {
        s_scal[0] = proj_b[0];
        s_scal[1] = fc_b[0] + linear_bias[0];
    }
    __syncthreads();

    // ---- gather embeddings as float4 ----
    for (int t = tid; t < NS * NF * 4; t += NTHREADS) {
        int s = t / (NF * 4);
        int rem = t - s * (NF * 4);
        int f = rem >> 2, q = rem & 3;
        const float4* src = (const float4*)embed_table;
        ((float4*)&s_emb[s][f][0])[q] = src[(long long)s_gid[s][f] * 4 + q];
    }
    __syncthreads();

    // ---- per-thread: pairs A=tid, B=tid+HPT, both samples, interleaved ----
    const bool active = (tid < HPT);
    float scA0 = -1e30f, scA1 = -1e30f, scB0 = -1e30f, scB1 = -1e30f;
    float gA0 = 0.f, gA1 = 0.f, gB0 = 0.f, gB1 = 0.f;

    if (active) {
        // decode both pairs
        int pA = tid, rA = 0, baseA = 0;
        while (pA >= baseA + (NF - 1 - rA)) { baseA += NF - 1 - rA; rA++; }
        int cA = rA + 1 + (pA - baseA);
        int pB = tid + HPT, rB = 0, baseB = 0;
        while (pB >= baseB + (NF - 1 - rB)) { baseB += NF - 1 - rB; rB++; }
        int cB = rB + 1 + (pB - baseB);

        float inA0[NE], inA1[NE], inB0[NE], inB1[NE];
        #pragma unroll
        for (int q = 0; q < 4; q++) {
            float4 a0 = ((const float4*)&s_emb[0][rA][0])[q];
            float4 c0 = ((const float4*)&s_emb[0][cA][0])[q];
            float4 a1 = ((const float4*)&s_emb[1][rA][0])[q];
            float4 c1 = ((const float4*)&s_emb[1][cA][0])[q];
            inA0[q*4+0]=a0.x*c0.x; inA0[q*4+1]=a0.y*c0.y; inA0[q*4+2]=a0.z*c0.z; inA0[q*4+3]=a0.w*c0.w;
            inA1[q*4+0]=a1.x*c1.x; inA1[q*4+1]=a1.y*c1.y; inA1[q*4+2]=a1.z*c1.z; inA1[q*4+3]=a1.w*c1.w;
            float4 b0v = ((const float4*)&s_emb[0][rB][0])[q];
            float4 d0 = ((const float4*)&s_emb[0][cB][0])[q];
            float4 b1v = ((const float4*)&s_emb[1][rB][0])[q];
            float4 d1 = ((const float4*)&s_emb[1][cB][0])[q];
            inB0[q*4+0]=b0v.x*d0.x; inB0[q*4+1]=b0v.y*d0.y; inB0[q*4+2]=b0v.z*d0.z; inB0[q*4+3]=b0v.w*d0.w;
            inB1[q*4+0]=b1v.x*d1.x; inB1[q*4+1]=b1v.y*d1.y; inB1[q*4+2]=b1v.z*d1.z; inB1[q*4+3]=b1v.w*d1.w;
        }

        // g = inner . fc_w  (4 streams)
        #pragma unroll
        for (int e = 0; e < NE; e++) {
            float fw = s_fcw[e];
            gA0 = fmaf(inA0[e], fw, gA0);
            gA1 = fmaf(inA1[e], fw, gA1);
            gB0 = fmaf(inB0[e], fw, gB0);
            gB1 = fmaf(inB1[e], fw, gB1);
        }

        // h = relu(inner @ W + b); s = h . proj_w + proj_b
        // 8 chunks of 4 attn cols = 2 packed f32x2 accumulators per stream
        // (small live set -> 4 CTAs/SM). W pairs load as LDS.64.
        float sA0 = s_scal[0], sA1 = s_scal[0], sB0 = s_scal[0], sB1 = s_scal[0];
        #pragma unroll
        for (int ch = 0; ch < 8; ch++) {
            const u64* bb = (const u64*)&s_attnb[ch*4];
            u64 hA0[2], hA1[2], hB0[2], hB1[2];
            #pragma unroll
            for (int j = 0; j < 2; j++) {
                u64 bj = bb[j];
                hA0[j] = bj; hA1[j] = bj; hB0[j] = bj; hB1[j] = bj;
            }

            #pragma unroll
            for (int e = 0; e < NE; e++) {
                const u64* wr = (const u64*)&s_W[e][ch*4];
                u64 iA0 = pack2(inA0[e], inA0[e]);
                u64 iA1 = pack2(inA1[e], inA1[e]);
                u64 iB0 = pack2(inB0[e], inB0[e]);
                u64 iB1 = pack2(inB1[e], inB1[e]);
                #pragma unroll
                for (int j = 0; j < 2; j++) {
                    u64 w = wr[j];
                    hA0[j] = fma2(iA0, w, hA0[j]);
                    hA1[j] = fma2(iA1, w, hA1[j]);
                    hB0[j] = fma2(iB0, w, hB0[j]);
                    hB1[j] = fma2(iB1, w, hB1[j]);
                }
            }

            #pragma unroll
            for (int j = 0; j < 2; j++) {
                float p0 = s_projw[ch*4 + j*2 + 0];
                float p1 = s_projw[ch*4 + j*2 + 1];
                float lo, hi;
                unpack2(hA0[j], lo, hi);
                sA0 = fmaf(fmaxf(lo,0.f), p0, sA0);
                sA0 = fmaf(fmaxf(hi,0.f), p1, sA0);
                unpack2(hA1[j], lo, hi);
                sA1 = fmaf(fmaxf(lo,0.f), p0, sA1);
                sA1 = fmaf(fmaxf(hi,0.f), p1, sA1);
                unpack2(hB0[j], lo, hi);
                sB0 = fmaf(fmaxf(lo,0.f), p0, sB0);
                sB0 = fmaf(fmaxf(hi,0.f), p1, sB0);
                unpack2(hB1[j], lo, hi);
                sB1 = fmaf(fmaxf(lo,0.f), p0, sB1);
                sB1 = fmaf(fmaxf(hi,0.f), p1, sB1);
            }
        }
        scA0 = sA0; scA1 = sA1; scB0 = sB0; scB1 = sB1;
    }

    // ---- block softmax-max reduction (both samples) ----
    float m0 = fmaxf(scA0, scB0);
    float m1 = fmaxf(scA1, scB1);
    #pragma unroll
    for (int o = 16; o > 0; o >>= 1) {
        m0 = fmaxf(m0, __shfl_xor_sync(0xffffffffu, m0, o));
        m1 = fmaxf(m1, __shfl_xor_sync(0xffffffffu, m1, o));
    }
    if (lane == 0) { red_max[0][wid] = m0; red_max[1][wid] = m1; }
    __syncthreads();
    if (tid == 0) {
        float a = red_max[0][0], b = red_max[1][0];
        #pragma unroll
        for (int w = 1; w < NWARP; w++) {
            a = fmaxf(a, red_max[0][w]);
            b = fmaxf(b, red_max[1][w]);
        }
        s_smax[0] = a; s_smax[1] = b;
    }
    __syncthreads();

    // ---- exp + weighted sums ----
    const float smax0 = s_smax[0], smax1 = s_smax[1];
    float exA0 = active ? __expf(scA0 - smax0) : 0.f;
    float exA1 = active ? __expf(scA1 - smax1) : 0.f;
    float exB0 = active ? __expf(scB0 - smax0) : 0.f;
    float exB1 = active ? __expf(scB1 - smax1) : 0.f;
    float se0 = exA0 + exB0;
    float se1 = exA1 + exB1;
    float sg0 = exA0 * gA0 + exB0 * gB0;
    float sg1 = exA1 * gA1 + exB1 * gB1;
    #pragma unroll
    for (int o = 16; o > 0; o >>= 1) {
        se0 += __shfl_xor_sync(0xffffffffu, se0, o);
        sg0 += __shfl_xor_sync(0xffffffffu, sg0, o);
        se1 += __shfl_xor_sync(0xffffffffu, se1, o);
        sg1 += __shfl_xor_sync(0xffffffffu, sg1, o);
    }
    if (lane == 0) {
        red_se[0][wid] = se0; red_sg[0][wid] = sg0;
        red_se[1][wid] = se1; red_sg[1][wid] = sg1;
    }
    __syncthreads();

    if (tid < NS) {
        int s = tid;
        float tse = 0.f, tsg = 0.f;
        #pragma unroll
        for (int w = 0; w < NWARP; w++) { tse += red_se[s][w]; tsg += red_sg[s][w]; }
        float lin = 0.f;
        #pragma unroll
        for (int f = 0; f < NF; f++) lin += s_lin[s][f];
        out[b0 + s] = lin + s_scal[1] + tsg / tse;
    }
}

extern "C" void kernel_launch(void* const* d_in, const int* in_sizes, int n_in,
                              void* d_out, int out_size) {
    const int* x              = (const int*)d_in[0];
    const float* embed_table  = (const float*)d_in[1];
    const float* linear_table = (const float*)d_in[2];
    const float* linear_bias  = (const float*)d_in[3];
    const float* attn_W       = (const float*)d_in[4];
    const float* attn_b       = (const float*)d_in[5];
    const float* proj_w       = (const float*)d_in[6];
    const float* proj_b       = (const float*)d_in[7];
    const float* fc_w         = (const float*)d_in[8];
    const float* fc_b         = (const float*)d_in[9];
    float* out = (float*)d_out;

    int B = out_size;                 // one output per sample
    int nblocks = (B + NS - 1) / NS;  // 16384 -> 8192
    afm_kernel<<<nblocks, NTHREADS>>>(x, embed_table, linear_table, linear_bias,
                                      attn_W, attn_b, proj_w, proj_b, fc_w, fc_b, out);
}

// round 12
// speedup vs baseline: 15.2445x; 1.9639x over previous
#include <cuda_runtime.h>
#include <cstdint>

// AFM forward: 2 samples per CTA, 2 pairs x 2 samples per thread (R9 structure),
// hidden GEMV via packed fma.rn.f32x2 with W loaded as ulonglong2 (LDS.128).
// cross term = (sum_p e^{s_p} g_p) / (sum_p e^{s_p}),  g_p = inner_p . fc_w

#define NF 24
#define NE 16
#define NA 32
#define NP 276            // 24*23/2
#define NS 2              // samples per block
#define HPT 138           // thread t handles pairs t and t+HPT
#define NTHREADS 160      // 5 warps
#define NWARP 5
#define EPAD 20           // padded row length for s_emb (80B)

typedef unsigned long long u64;

__device__ __forceinline__ u64 pack2(float lo, float hi) {
    u64 r;
    asm("mov.b64 %0, {%1, %2};" : "=l"(r) : "f"(lo), "f"(hi));
    return r;
}
__device__ __forceinline__ void unpack2(u64 v, float& lo, float& hi) {
    asm("mov.b64 {%0, %1}, %2;" : "=f"(lo), "=f"(hi) : "l"(v));
}
__device__ __forceinline__ u64 fma2(u64 a, u64 b, u64 c) {
    u64 d;
    asm("fma.rn.f32x2 %0, %1, %2, %3;" : "=l"(d) : "l"(a), "l"(b), "l"(c));
    return d;
}

__global__ __launch_bounds__(NTHREADS, 3) void afm_kernel(
    const int* __restrict__ x_raw,            // [B,24] int32 OR int64 (auto-detect)
    const float* __restrict__ embed_table,    // [V,16]
    const float* __restrict__ linear_table,   // [V,1]
    const float* __restrict__ linear_bias,    // [1]
    const float* __restrict__ attn_W,         // [16,32]
    const float* __restrict__ attn_b,         // [32]
    const float* __restrict__ proj_w,         // [32,1]
    const float* __restrict__ proj_b,         // [1]
    const float* __restrict__ fc_w,           // [16,1]
    const float* __restrict__ fc_b,           // [1]
    float* __restrict__ out)                  // [B,1]
{
    __shared__ __align__(16) float s_emb[NS][NF][EPAD];
    __shared__ __align__(16) float s_W[NE][NA];
    __shared__ __align__(16) float s_attnb[NA];
    __shared__ __align__(16) float s_projw[NA];
    __shared__ __align__(16) float s_fcw[NE];
    __shared__ int   s_gid[NS][NF];
    __shared__ float s_lin[NS][NF];
    __shared__ float s_scal[2];
    __shared__ float red_max[NS][NWARP];
    __shared__ float red_se[NS][NWARP];
    __shared__ float red_sg[NS][NWARP];
    __shared__ float s_smax[NS];

    const int tid  = threadIdx.x;
    const int wid  = tid >> 5;
    const int lane = tid & 31;
    const long long b0 = (long long)blockIdx.x * NS;

    // dtype probe: int64 values < 50000 have zero high words at odd positions.
    const bool is64 = (x_raw[1] == 0) & (x_raw[3] == 0) & (x_raw[5] == 0) & (x_raw[7] == 0);

    // ---- stage indices + linear terms ----
    if (tid < NS * NF) {
        int s = tid / NF;
        int f = tid - s * NF;
        long long flat = (b0 + s) * NF + f;
        int xv = is64 ? x_raw[flat * 2] : x_raw[flat];
        int gid = xv + f * 50000;
        s_gid[s][f] = gid;
        s_lin[s][f] = linear_table[gid];
    }
    for (int t = tid; t < NE * NA; t += NTHREADS)
        ((float*)s_W)[t] = attn_W[t];
    if (tid < NA) {
        s_attnb[tid] = attn_b[tid];
        s_projw[tid] = proj_w[tid];
    }
    if (tid < NE) s_fcw[tid] = fc_w[tid];
    if (tid == 0) {
        s_scal[0] = proj_b[0];
        s_scal[1] = fc_b[0] + linear_bias[0];
    }
    __syncthreads();

    // ---- gather embeddings as float4 ----
    for (int t = tid; t < NS * NF * 4; t += NTHREADS) {
        int s = t / (NF * 4);
        int rem = t - s * (NF * 4);
        int f = rem >> 2, q = rem & 3;
        const float4* src = (const float4*)embed_table;
        ((float4*)&s_emb[s][f][0])[q] = src[(long long)s_gid[s][f] * 4 + q];
    }
    __syncthreads();

    // ---- per-thread: pairs A=tid, B=tid+HPT, both samples, interleaved ----
    const bool active = (tid < HPT);
    float scA0 = -1e30f, scA1 = -1e30f, scB0 = -1e30f, scB1 = -1e30f;
    float gA0 = 0.f, gA1 = 0.f, gB0 = 0.f, gB1 = 0.f;

    if (active) {
        // decode both pairs
        int pA = tid, rA = 0, baseA = 0;
        while (pA >= baseA + (NF - 1 - rA)) { baseA += NF - 1 - rA; rA++; }
        int cA = rA + 1 + (pA - baseA);
        int pB = tid + HPT, rB = 0, baseB = 0;
        while (pB >= baseB + (NF - 1 - rB)) { baseB += NF - 1 - rB; rB++; }
        int cB = rB + 1 + (pB - baseB);

        float inA0[NE], inA1[NE], inB0[NE], inB1[NE];
        #pragma unroll
        for (int q = 0; q < 4; q++) {
            float4 a0 = ((const float4*)&s_emb[0][rA][0])[q];
            float4 c0 = ((const float4*)&s_emb[0][cA][0])[q];
            float4 a1 = ((const float4*)&s_emb[1][rA][0])[q];
            float4 c1 = ((const float4*)&s_emb[1][cA][0])[q];
            inA0[q*4+0]=a0.x*c0.x; inA0[q*4+1]=a0.y*c0.y; inA0[q*4+2]=a0.z*c0.z; inA0[q*4+3]=a0.w*c0.w;
            inA1[q*4+0]=a1.x*c1.x; inA1[q*4+1]=a1.y*c1.y; inA1[q*4+2]=a1.z*c1.z; inA1[q*4+3]=a1.w*c1.w;
            float4 b0v = ((const float4*)&s_emb[0][rB][0])[q];
            float4 d0 = ((const float4*)&s_emb[0][cB][0])[q];
            float4 b1v = ((const float4*)&s_emb[1][rB][0])[q];
            float4 d1 = ((const float4*)&s_emb[1][cB][0])[q];
            inB0[q*4+0]=b0v.x*d0.x; inB0[q*4+1]=b0v.y*d0.y; inB0[q*4+2]=b0v.z*d0.z; inB0[q*4+3]=b0v.w*d0.w;
            inB1[q*4+0]=b1v.x*d1.x; inB1[q*4+1]=b1v.y*d1.y; inB1[q*4+2]=b1v.z*d1.z; inB1[q*4+3]=b1v.w*d1.w;
        }

        // g = inner . fc_w  (4 streams)
        #pragma unroll
        for (int e = 0; e < NE; e++) {
            float fw = s_fcw[e];
            gA0 = fmaf(inA0[e], fw, gA0);
            gA1 = fmaf(inA1[e], fw, gA1);
            gB0 = fmaf(inB0[e], fw, gB0);
            gB1 = fmaf(inB1[e], fw, gB1);
        }

        // h = relu(inner @ W + b); s = h . proj_w + proj_b
        // 4 chunks of 8 attn cols = 4 packed f32x2 accumulators per stream.
        // W/bias read as ulonglong2 (LDS.128) -> halves load instruction count;
        // each half is an even-aligned u64 pair directly usable by fma2.
        float sA0 = s_scal[0], sA1 = s_scal[0], sB0 = s_scal[0], sB1 = s_scal[0];
        #pragma unroll
        for (int ch = 0; ch < 4; ch++) {
            ulonglong2 bv0 = ((const ulonglong2*)&s_attnb[ch*8])[0];
            ulonglong2 bv1 = ((const ulonglong2*)&s_attnb[ch*8])[1];
            u64 hA0[4], hA1[4], hB0[4], hB1[4];
            hA0[0]=bv0.x; hA0[1]=bv0.y; hA0[2]=bv1.x; hA0[3]=bv1.y;
            hA1[0]=bv0.x; hA1[1]=bv0.y; hA1[2]=bv1.x; hA1[3]=bv1.y;
            hB0[0]=bv0.x; hB0[1]=bv0.y; hB0[2]=bv1.x; hB0[3]=bv1.y;
            hB1[0]=bv0.x; hB1[1]=bv0.y; hB1[2]=bv1.x; hB1[3]=bv1.y;

            #pragma unroll
            for (int e = 0; e < NE; e++) {
                const ulonglong2* wr = (const ulonglong2*)&s_W[e][ch*8];
                ulonglong2 wa = wr[0];           // LDS.128: cols 0-3 of chunk
                ulonglong2 wb = wr[1];           // LDS.128: cols 4-7 of chunk
                u64 iA0 = pack2(inA0[e], inA0[e]);
                u64 iA1 = pack2(inA1[e], inA1[e]);
                u64 iB0 = pack2(inB0[e], inB0[e]);
                u64 iB1 = pack2(inB1[e], inB1[e]);
                hA0[0] = fma2(iA0, wa.x, hA0[0]);
                hA1[0] = fma2(iA1, wa.x, hA1[0]);
                hB0[0] = fma2(iB0, wa.x, hB0[0]);
                hB1[0] = fma2(iB1, wa.x, hB1[0]);
                hA0[1] = fma2(iA0, wa.y, hA0[1]);
                hA1[1] = fma2(iA1, wa.y, hA1[1]);
                hB0[1] = fma2(iB0, wa.y, hB0[1]);
                hB1[1] = fma2(iB1, wa.y, hB1[1]);
                hA0[2] = fma2(iA0, wb.x, hA0[2]);
                hA1[2] = fma2(iA1, wb.x, hA1[2]);
                hB0[2] = fma2(iB0, wb.x, hB0[2]);
                hB1[2] = fma2(iB1, wb.x, hB1[2]);
                hA0[3] = fma2(iA0, wb.y, hA0[3]);
                hA1[3] = fma2(iA1, wb.y, hA1[3]);
                hB0[3] = fma2(iB0, wb.y, hB0[3]);
                hB1[3] = fma2(iB1, wb.y, hB1[3]);
            }

            #pragma unroll
            for (int j = 0; j < 4; j++) {
                float p0 = s_projw[ch*8 + j*2 + 0];
                float p1 = s_projw[ch*8 + j*2 + 1];
                float lo, hi;
                unpack2(hA0[j], lo, hi);
                sA0 = fmaf(fmaxf(lo,0.f), p0, sA0);
                sA0 = fmaf(fmaxf(hi,0.f), p1, sA0);
                unpack2(hA1[j], lo, hi);
                sA1 = fmaf(fmaxf(lo,0.f), p0, sA1);
                sA1 = fmaf(fmaxf(hi,0.f), p1, sA1);
                unpack2(hB0[j], lo, hi);
                sB0 = fmaf(fmaxf(lo,0.f), p0, sB0);
                sB0 = fmaf(fmaxf(hi,0.f), p1, sB0);
                unpack2(hB1[j], lo, hi);
                sB1 = fmaf(fmaxf(lo,0.f), p0, sB1);
                sB1 = fmaf(fmaxf(hi,0.f), p1, sB1);
            }
        }
        scA0 = sA0; scA1 = sA1; scB0 = sB0; scB1 = sB1;
    }

    // ---- block softmax-max reduction (both samples) ----
    float m0 = fmaxf(scA0, scB0);
    float m1 = fmaxf(scA1, scB1);
    #pragma unroll
    for (int o = 16; o > 0; o >>= 1) {
        m0 = fmaxf(m0, __shfl_xor_sync(0xffffffffu, m0, o));
        m1 = fmaxf(m1, __shfl_xor_sync(0xffffffffu, m1, o));
    }
    if (lane == 0) { red_max[0][wid] = m0; red_max[1][wid] = m1; }
    __syncthreads();
    if (tid == 0) {
        float a = red_max[0][0], b = red_max[1][0];
        #pragma unroll
        for (int w = 1; w < NWARP; w++) {
            a = fmaxf(a, red_max[0][w]);
            b = fmaxf(b, red_max[1][w]);
        }
        s_smax[0] = a; s_smax[1] = b;
    }
    __syncthreads();

    // ---- exp + weighted sums ----
    const float smax0 = s_smax[0], smax1 = s_smax[1];
    float exA0 = active ? __expf(scA0 - smax0) : 0.f;
    float exA1 = active ? __expf(scA1 - smax1) : 0.f;
    float exB0 = active ? __expf(scB0 - smax0) : 0.f;
    float exB1 = active ? __expf(scB1 - smax1) : 0.f;
    float se0 = exA0 + exB0;
    float se1 = exA1 + exB1;
    float sg0 = exA0 * gA0 + exB0 * gB0;
    float sg1 = exA1 * gA1 + exB1 * gB1;
    #pragma unroll
    for (int o = 16; o > 0; o >>= 1) {
        se0 += __shfl_xor_sync(0xffffffffu, se0, o);
        sg0 += __shfl_xor_sync(0xffffffffu, sg0, o);
        se1 += __shfl_xor_sync(0xffffffffu, se1, o);
        sg1 += __shfl_xor_sync(0xffffffffu, sg1, o);
    }
    if (lane == 0) {
        red_se[0][wid] = se0; red_sg[0][wid] = sg0;
        red_se[1][wid] = se1; red_sg[1][wid] = sg1;
    }
    __syncthreads();

    if (tid < NS) {
        int s = tid;
        float tse = 0.f, tsg = 0.f;
        #pragma unroll
        for (int w = 0; w < NWARP; w++) { tse += red_se[s][w]; tsg += red_sg[s][w]; }
        float lin = 0.f;
        #pragma unroll
        for (int f = 0; f < NF; f++) lin += s_lin[s][f];
        out[b0 + s] = lin + s_scal[1] + tsg / tse;
    }
}

extern "C" void kernel_launch(void* const* d_in, const int* in_sizes, int n_in,
                              void* d_out, int out_size) {
    const int* x              = (const int*)d_in[0];
    const float* embed_table  = (const float*)d_in[1];
    const float* linear_table = (const float*)d_in[2];
    const float* linear_bias  = (const float*)d_in[3];
    const float* attn_W       = (const float*)d_in[4];
    const float* attn_b       = (const float*)d_in[5];
    const float* proj_w       = (const float*)d_in[6];
    const float* proj_b       = (const float*)d_in[7];
    const float* fc_w         = (const float*)d_in[8];
    const float* fc_b         = (const float*)d_in[9];
    float* out = (float*)d_out;

    int B = out_size;                 // one output per sample
    int nblocks = (B + NS - 1) / NS;  // 16384 -> 8192
    afm_kernel<<<nblocks, NTHREADS>>>(x, embed_table, linear_table, linear_bias,
                                      attn_W, attn_b, proj_w, proj_b, fc_w, fc_b, out);
}